// round 10
// baseline (speedup 1.0000x reference)
#include <cuda_runtime.h>
#include <cuda_fp16.h>
#include <cstdint>

// Problem constants (from reference setup_inputs)
#define NMAX 8192
#define D    128
#define MASK_WORDS ((size_t)NMAX * NMAX / 32)   // 2,097,152 words = 8 MB
#define CAP  2048                               // neighbor-list capacity per row

// Scratch (static device globals — no allocation in kernel_launch)
__device__ unsigned g_mask[MASK_WORDS];          // adjacency bitmask, row = src
__device__ int      g_deg[NMAX];                 // distinct-neighbor degree (incl. self loop)
__device__ int      g_cnt[NMAX];                 // extracted list length
__device__ unsigned short g_adj[(size_t)NMAX * CAP]; // per-row neighbor lists (32 MB)
__device__ __half2  g_yh[NMAX * 64];             // y' = dinv[row]*(x@W^T)[row], fp16
__device__ float2   g_wt2[64 * D];               // W^T packed k-pair-interleaved

// packed dual-fp32 fma: d.lo += a.lo*b.lo ; d.hi += a.hi*b.hi
__device__ __forceinline__ void ffma2(unsigned long long& d,
                                      unsigned long long a,
                                      unsigned long long b) {
    asm("fma.rn.f32x2 %0, %1, %2, %0;" : "+l"(d) : "l"(a), "l"(b));
}
__device__ __forceinline__ float f32x2_hsum(unsigned long long v) {
    float lo, hi;
    asm("mov.b64 {%0,%1}, %2;" : "=f"(lo), "=f"(hi) : "l"(v));
    return lo + hi;
}
// packed fp16 add on raw uint32 half2 bits
__device__ __forceinline__ unsigned hadd2(unsigned a, unsigned b) {
    unsigned r;
    asm("add.rn.f16x2 %0, %1, %2;" : "=r"(r) : "r"(a), "r"(b));
    return r;
}

// ---------------------------------------------------------------------------
// 1) zero mask + degree + cnt, AND pack Wt2 (independent of the graph)
__global__ void k_zero(const float* __restrict__ W, int n_words, int n) {
    int i = blockIdx.x * blockDim.x + threadIdx.x;
    int stride = gridDim.x * blockDim.x;
    uint4* m4 = reinterpret_cast<uint4*>(g_mask);
    int nw4 = n_words >> 2;
    uint4 z = make_uint4(0u, 0u, 0u, 0u);
    for (int w = i; w < nw4; w += stride) m4[w] = z;
    for (int v = i; v < n; v += stride) { g_deg[v] = 0; g_cnt[v] = 0; }
    if (i < 64 * D) {
        int col = i & 127;
        int kp  = i >> 7;
        g_wt2[kp * D + col] = make_float2(W[col * D + 2 * kp],
                                          W[col * D + 2 * kp + 1]);
    }
}

// ---------------------------------------------------------------------------
// 2) set bits for edges (+ self loops), count degrees on first-set only (dedup)
//    edge_index is int32 (JAX x64-disabled downcasts the requested int64)
__global__ void k_build(const int* __restrict__ edge, int E, int N) {
    int t = blockIdx.x * blockDim.x + threadIdx.x;
    int total = E + N;
    if (t >= total) return;
    int s, d;
    if (t < E) {
        s = edge[t];        // edge_index[0, t] = src
        d = edge[E + t];    // edge_index[1, t] = dst
    } else {
        s = d = t - E;      // self loop
    }
    s &= (NMAX - 1);
    d &= (NMAX - 1);
    int bitpos = s * N + d;
    unsigned bit = 1u << (bitpos & 31);
    unsigned old = atomicOr(&g_mask[bitpos >> 5], bit);
    if (!(old & bit)) atomicAdd(&g_deg[s], 1);
}

// ---------------------------------------------------------------------------
// 3) extract ordered neighbor lists: one WARP per row, shuffle-scan only.
//    Deterministic ascending bit order. ~33 entries per row.
__global__ void k_extract(int N) {
    int warp = (blockIdx.x * blockDim.x + threadIdx.x) >> 5;
    int lane = threadIdx.x & 31;
    if (warp >= N) return;
    int words = N >> 5;                       // 256
    const unsigned* mrow = g_mask + (size_t)warp * words;
    unsigned short* dst = g_adj + (size_t)warp * CAP;

    int running = 0;
    for (int c = 0; c < words; c += 32) {
        unsigned m = mrow[c + lane];          // coalesced
        int cnt = __popc(m);
        // warp inclusive scan
        int inc = cnt;
        #pragma unroll
        for (int dd = 1; dd < 32; dd <<= 1) {
            int v = __shfl_up_sync(0xffffffffu, inc, dd);
            if (lane >= dd) inc += v;
        }
        int total = __shfl_sync(0xffffffffu, inc, 31);
        int off = running + inc - cnt;        // exclusive offset
        int base = (c + lane) << 5;
        while (m) {
            int b = __ffs(m) - 1; m &= m - 1;
            if (off < CAP) dst[off] = (unsigned short)(base + b);
            off++;
        }
        running += total;
    }
    if (lane == 0) g_cnt[warp] = running;
}

// ---------------------------------------------------------------------------
// 4) y' = dinv .* (x @ W^T)  via packed f32x2 FMA, fp16 output.
#define BR 16
__global__ void __launch_bounds__(256) k_gemm_y(const float* __restrict__ x, int N) {
    __shared__ float4 xs[BR * 32];   // [row][kk4], 8 KB

    int t = threadIdx.x;             // 0..255
    int row0 = blockIdx.x * BR;

    const float4* xg = reinterpret_cast<const float4*>(x) + (size_t)row0 * 32;
    int lim = (N - row0) * 32;
    xs[t]       = (t < lim)       ? xg[t]       : make_float4(0.f, 0.f, 0.f, 0.f);
    xs[t + 256] = (t + 256 < lim) ? xg[t + 256] : make_float4(0.f, 0.f, 0.f, 0.f);
    __syncthreads();

    int cp = t & 63;                 // col-pair: cols 2cp, 2cp+1
    int ry = t >> 6;                 // 0..3 -> rows 4ry..4ry+3
    int r0 = 4 * ry;

    const ulonglong2* xv = reinterpret_cast<const ulonglong2*>(xs);
    const ulonglong2* wv = reinterpret_cast<const ulonglong2*>(g_wt2);

    unsigned long long acc[4][2];
    #pragma unroll
    for (int r = 0; r < 4; r++) { acc[r][0] = 0ull; acc[r][1] = 0ull; }

    ulonglong2 w0 = wv[0 * 64 + cp];
    ulonglong2 w1 = wv[1 * 64 + cp];

    #pragma unroll
    for (int kk = 0; kk < 32; kk++) {
        ulonglong2 nw0, nw1;
        if (kk < 31) {
            nw0 = wv[(2 * kk + 2) * 64 + cp];
            nw1 = wv[(2 * kk + 3) * 64 + cp];
        }
        #pragma unroll
        for (int r = 0; r < 4; r++) {
            ulonglong2 xa = xv[(r0 + r) * 32 + kk];
            ffma2(acc[r][0], xa.x, w0.x); ffma2(acc[r][1], xa.x, w0.y);
            ffma2(acc[r][0], xa.y, w1.x); ffma2(acc[r][1], xa.y, w1.y);
        }
        w0 = nw0; w1 = nw1;
    }

    #pragma unroll
    for (int r = 0; r < 4; r++) {
        int row = row0 + r0 + r;
        if (row < N) {
            float dv = rsqrtf((float)g_deg[row] + 1e-8f);
            float sx = f32x2_hsum(acc[r][0]) * dv;
            float sy = f32x2_hsum(acc[r][1]) * dv;
            g_yh[(size_t)row * 64 + cp] = __floats2half2_rn(sx, sy);
        }
    }
}

// ---------------------------------------------------------------------------
// 5) out[i] = dinv[i] * sum_{j in nbr(i)} y'[j]  + b   — pure gather now.
//    8 streams x 16 threads, uint4 (8 cols) per neighbor, HADD2 tree per 4
//    neighbors, fp32 master accumulators, fixed-order reduce. Deterministic.
__global__ void k_aggregate(const float* __restrict__ bias,
                            float* __restrict__ out, int N) {
    int i = blockIdx.x;
    int t = threadIdx.x;   // 0..127

    __shared__ unsigned short nbr[CAP];      // 4 KB
    __shared__ float2 part[8 * 64];          // 4 KB  [group][half2-col]

    int K = g_cnt[i];

    // load list (coalesced 32-bit loads, 2 entries each)
    if (K <= CAP) {
        const unsigned* src = reinterpret_cast<const unsigned*>(g_adj + (size_t)i * CAP);
        unsigned* l32 = reinterpret_cast<unsigned*>(nbr);
        int nw = (K + 1) >> 1;
        for (int w = t; w < nw; w += 128) l32[w] = src[w];
    }
    __syncthreads();

    int g = t >> 4;    // 0..7: neighbor stream (walks k = g, g+8, g+16, ...)
    int c = t & 15;    // col chunk: half2 cols 4c..4c+3

    const uint4* yv = reinterpret_cast<const uint4*>(g_yh);   // [row][16]

    float2 f0 = make_float2(0.f, 0.f), f1 = f0, f2 = f0, f3 = f0;

    if (K <= CAP) {
        int k = g;
        for (; k + 24 < K; k += 32) {
            int j0 = nbr[k], j1 = nbr[k + 8], j2 = nbr[k + 16], j3 = nbr[k + 24];
            uint4 v0 = yv[j0 * 16 + c];
            uint4 v1 = yv[j1 * 16 + c];
            uint4 v2 = yv[j2 * 16 + c];
            uint4 v3 = yv[j3 * 16 + c];
            unsigned s0 = hadd2(hadd2(v0.x, v1.x), hadd2(v2.x, v3.x));
            unsigned s1 = hadd2(hadd2(v0.y, v1.y), hadd2(v2.y, v3.y));
            unsigned s2 = hadd2(hadd2(v0.z, v1.z), hadd2(v2.z, v3.z));
            unsigned s3 = hadd2(hadd2(v0.w, v1.w), hadd2(v2.w, v3.w));
            float2 q0 = __half22float2(*reinterpret_cast<__half2*>(&s0));
            float2 q1 = __half22float2(*reinterpret_cast<__half2*>(&s1));
            float2 q2 = __half22float2(*reinterpret_cast<__half2*>(&s2));
            float2 q3 = __half22float2(*reinterpret_cast<__half2*>(&s3));
            f0.x += q0.x; f0.y += q0.y;
            f1.x += q1.x; f1.y += q1.y;
            f2.x += q2.x; f2.y += q2.y;
            f3.x += q3.x; f3.y += q3.y;
        }
        for (; k < K; k += 8) {
            uint4 v = yv[nbr[k] * 16 + c];
            float2 q0 = __half22float2(*reinterpret_cast<__half2*>(&v.x));
            float2 q1 = __half22float2(*reinterpret_cast<__half2*>(&v.y));
            float2 q2 = __half22float2(*reinterpret_cast<__half2*>(&v.z));
            float2 q3 = __half22float2(*reinterpret_cast<__half2*>(&v.w));
            f0.x += q0.x; f0.y += q0.y;
            f1.x += q1.x; f1.y += q1.y;
            f2.x += q2.x; f2.y += q2.y;
            f3.x += q3.x; f3.y += q3.y;
        }
    } else {
        // overflow fallback — structurally impossible here, kept for safety.
        // group 0 serially scans the mask row from global.
        if (g == 0) {
            int words = N >> 5;
            for (int w = 0; w < words; w++) {
                unsigned m = g_mask[(size_t)i * words + w];
                while (m) {
                    int b = __ffs(m) - 1; m &= m - 1;
                    int j = (w << 5) + b;
                    uint4 v = yv[j * 16 + c];
                    float2 q0 = __half22float2(*reinterpret_cast<__half2*>(&v.x));
                    float2 q1 = __half22float2(*reinterpret_cast<__half2*>(&v.y));
                    float2 q2 = __half22float2(*reinterpret_cast<__half2*>(&v.z));
                    float2 q3 = __half22float2(*reinterpret_cast<__half2*>(&v.w));
                    f0.x += q0.x; f0.y += q0.y;
                    f1.x += q1.x; f1.y += q1.y;
                    f2.x += q2.x; f2.y += q2.y;
                    f3.x += q3.x; f3.y += q3.y;
                }
            }
        }
    }

    part[g * 64 + 4 * c + 0] = f0;
    part[g * 64 + 4 * c + 1] = f1;
    part[g * 64 + 4 * c + 2] = f2;
    part[g * 64 + 4 * c + 3] = f3;
    __syncthreads();

    if (t < 64) {
        float2 s = part[t];
        #pragma unroll
        for (int q = 1; q < 8; q++) {
            float2 pv = part[q * 64 + t];
            s.x += pv.x; s.y += pv.y;
        }
        float dv = rsqrtf((float)g_deg[i] + 1e-8f);
        float2 bb = reinterpret_cast<const float2*>(bias)[t];
        float2 o;
        o.x = fmaf(dv, s.x, bb.x);
        o.y = fmaf(dv, s.y, bb.y);
        reinterpret_cast<float2*>(out)[(size_t)i * 64 + t] = o;
    }
}

// ---------------------------------------------------------------------------
extern "C" void kernel_launch(void* const* d_in, const int* in_sizes, int n_in,
                              void* d_out, int out_size) {
    const float* x    = (const float*)d_in[0];
    const int*   edge = (const int*)d_in[1];
    const float* W    = (const float*)d_in[2];
    const float* b    = (const float*)d_in[3];
    float*       out  = (float*)d_out;

    int N = in_sizes[0] / D;        // 8192
    int E = in_sizes[1] / 2;        // 262144
    int n_words = (N * N) >> 5;

    k_zero<<<1024, 256>>>(W, n_words, N);
    int total = E + N;
    k_build<<<(total + 255) / 256, 256>>>(edge, E, N);
    k_extract<<<(N * 32 + 255) / 256, 256>>>(N);
    k_gemm_y<<<(N + BR - 1) / BR, 256>>>(x, N);
    k_aggregate<<<N, D>>>(b, out, N);
}

// round 11
// speedup vs baseline: 1.1546x; 1.1546x over previous
#include <cuda_runtime.h>
#include <cuda_fp16.h>
#include <cstdint>

// Problem constants (from reference setup_inputs)
#define NMAX 8192
#define D    128
#define MASK_WORDS ((size_t)NMAX * NMAX / 32)   // 2,097,152 words = 8 MB
#define CAP  2048                               // neighbor-list capacity per row

// Scratch (static device globals — no allocation in kernel_launch)
__device__ unsigned g_mask[MASK_WORDS];          // adjacency bitmask, row = src
__device__ int      g_deg[NMAX];                 // distinct-neighbor degree (incl. self loop)
__device__ __half2  g_yh[NMAX * 64];             // y' = dinv[row]*(x@W^T)[row], fp16
__device__ float2   g_wt2[64 * D];               // W^T packed k-pair-interleaved

// packed dual-fp32 fma: d.lo += a.lo*b.lo ; d.hi += a.hi*b.hi
__device__ __forceinline__ void ffma2(unsigned long long& d,
                                      unsigned long long a,
                                      unsigned long long b) {
    asm("fma.rn.f32x2 %0, %1, %2, %0;" : "+l"(d) : "l"(a), "l"(b));
}
__device__ __forceinline__ float f32x2_hsum(unsigned long long v) {
    float lo, hi;
    asm("mov.b64 {%0,%1}, %2;" : "=f"(lo), "=f"(hi) : "l"(v));
    return lo + hi;
}
// packed fp16 add on raw uint32 half2 bits
__device__ __forceinline__ unsigned hadd2(unsigned a, unsigned b) {
    unsigned r;
    asm("add.rn.f16x2 %0, %1, %2;" : "=r"(r) : "r"(a), "r"(b));
    return r;
}

// ---------------------------------------------------------------------------
// 1) zero mask + degree, AND pack Wt2 (independent of the graph)
__global__ void k_zero(const float* __restrict__ W, int n_words, int n) {
    int i = blockIdx.x * blockDim.x + threadIdx.x;
    int stride = gridDim.x * blockDim.x;
    uint4* m4 = reinterpret_cast<uint4*>(g_mask);
    int nw4 = n_words >> 2;
    uint4 z = make_uint4(0u, 0u, 0u, 0u);
    for (int w = i; w < nw4; w += stride) m4[w] = z;
    for (int v = i; v < n; v += stride) g_deg[v] = 0;
    if (i < 64 * D) {
        int col = i & 127;
        int kp  = i >> 7;
        g_wt2[kp * D + col] = make_float2(W[col * D + 2 * kp],
                                          W[col * D + 2 * kp + 1]);
    }
}

// ---------------------------------------------------------------------------
// 2) set bits for edges (+ self loops), count degrees on first-set only (dedup)
//    edge_index is int32 (JAX x64-disabled downcasts the requested int64)
__global__ void k_build(const int* __restrict__ edge, int E, int N) {
    int t = blockIdx.x * blockDim.x + threadIdx.x;
    int total = E + N;
    if (t >= total) return;
    int s, d;
    if (t < E) {
        s = edge[t];        // edge_index[0, t] = src
        d = edge[E + t];    // edge_index[1, t] = dst
    } else {
        s = d = t - E;      // self loop
    }
    s &= (NMAX - 1);
    d &= (NMAX - 1);
    int bitpos = s * N + d;
    unsigned bit = 1u << (bitpos & 31);
    unsigned old = atomicOr(&g_mask[bitpos >> 5], bit);
    if (!(old & bit)) atomicAdd(&g_deg[s], 1);
}

// ---------------------------------------------------------------------------
// 3) y' = dinv .* (x @ W^T)  via packed f32x2 FMA, fp16 output.
//    16 rows/block, 256 threads: cp = t&63 -> cols (2cp, 2cp+1),
//    ry = t>>6 -> rows 4ry..4ry+3. W prefetched one kk ahead; the 4 broadcast
//    LDS reads are batched ahead of the FMA block.
#define BR 16
__global__ void __launch_bounds__(256) k_gemm_y(const float* __restrict__ x, int N) {
    __shared__ float4 xs[BR * 32];   // [row][kk4], 8 KB

    int t = threadIdx.x;             // 0..255
    int row0 = blockIdx.x * BR;

    const float4* xg = reinterpret_cast<const float4*>(x) + (size_t)row0 * 32;
    int lim = (N - row0) * 32;
    xs[t]       = (t < lim)       ? xg[t]       : make_float4(0.f, 0.f, 0.f, 0.f);
    xs[t + 256] = (t + 256 < lim) ? xg[t + 256] : make_float4(0.f, 0.f, 0.f, 0.f);
    __syncthreads();

    int cp = t & 63;                 // col-pair: cols 2cp, 2cp+1
    int ry = t >> 6;                 // 0..3 -> rows 4ry..4ry+3
    int r0 = 4 * ry;

    const ulonglong2* xv = reinterpret_cast<const ulonglong2*>(xs);
    const ulonglong2* wv = reinterpret_cast<const ulonglong2*>(g_wt2);

    unsigned long long acc[4][2];
    #pragma unroll
    for (int r = 0; r < 4; r++) { acc[r][0] = 0ull; acc[r][1] = 0ull; }

    ulonglong2 w0 = wv[0 * 64 + cp];
    ulonglong2 w1 = wv[1 * 64 + cp];

    #pragma unroll
    for (int kk = 0; kk < 32; kk++) {
        // batch the 4 broadcast LDS reads up front (independent, 1 wf each)
        ulonglong2 xa0 = xv[(r0 + 0) * 32 + kk];
        ulonglong2 xa1 = xv[(r0 + 1) * 32 + kk];
        ulonglong2 xa2 = xv[(r0 + 2) * 32 + kk];
        ulonglong2 xa3 = xv[(r0 + 3) * 32 + kk];
        ulonglong2 nw0, nw1;
        if (kk < 31) {                          // prefetch next W pair
            nw0 = wv[(2 * kk + 2) * 64 + cp];
            nw1 = wv[(2 * kk + 3) * 64 + cp];
        }
        ffma2(acc[0][0], xa0.x, w0.x); ffma2(acc[0][1], xa0.x, w0.y);
        ffma2(acc[1][0], xa1.x, w0.x); ffma2(acc[1][1], xa1.x, w0.y);
        ffma2(acc[2][0], xa2.x, w0.x); ffma2(acc[2][1], xa2.x, w0.y);
        ffma2(acc[3][0], xa3.x, w0.x); ffma2(acc[3][1], xa3.x, w0.y);
        ffma2(acc[0][0], xa0.y, w1.x); ffma2(acc[0][1], xa0.y, w1.y);
        ffma2(acc[1][0], xa1.y, w1.x); ffma2(acc[1][1], xa1.y, w1.y);
        ffma2(acc[2][0], xa2.y, w1.x); ffma2(acc[2][1], xa2.y, w1.y);
        ffma2(acc[3][0], xa3.y, w1.x); ffma2(acc[3][1], xa3.y, w1.y);
        w0 = nw0; w1 = nw1;
    }

    #pragma unroll
    for (int r = 0; r < 4; r++) {
        int row = row0 + r0 + r;
        if (row < N) {
            float dv = rsqrtf((float)g_deg[row] + 1e-8f);
            float sx = f32x2_hsum(acc[r][0]) * dv;
            float sy = f32x2_hsum(acc[r][1]) * dv;
            g_yh[(size_t)row * 64 + cp] = __floats2half2_rn(sx, sy);
        }
    }
}

// ---------------------------------------------------------------------------
// 4) out[i] = dinv[i] * sum_{j in nbr(i)} y'[j]  + b
//    Phase A (lean): thread t loads its two mask words as one uint2 LDG.64
//    straight from global, scans, emits ordered list to smem. 3 syncs total.
//    Phase B: 8 streams x 16 threads, uint4 per neighbor, HADD2 tree per 4,
//    fp32 master accumulators, fixed-order reduce. Deterministic.
__global__ void k_aggregate(const float* __restrict__ bias,
                            float* __restrict__ out, int N) {
    int i = blockIdx.x;
    int t = threadIdx.x;   // 0..127
    int words = N >> 5;    // 256

    __shared__ unsigned short nbr[CAP];      // 4 KB
    __shared__ float2 part[8 * 64];          // 4 KB
    __shared__ int wsum[4];
    __shared__ int totK;

    // direct global load: thread t owns words 2t, 2t+1 (coalesced uint2)
    const uint2* mrow = reinterpret_cast<const uint2*>(g_mask + (size_t)i * words);
    uint2 mw = mrow[t];
    unsigned m0 = mw.x, m1 = mw.y;
    int cnt = __popc(m0) + __popc(m1);

    // inclusive warp scan of counts
    int lane = t & 31, wid = t >> 5;
    int inc = cnt;
    #pragma unroll
    for (int dd = 1; dd < 32; dd <<= 1) {
        int v = __shfl_up_sync(0xffffffffu, inc, dd);
        if (lane >= dd) inc += v;
    }
    if (lane == 31) wsum[wid] = inc;
    __syncthreads();
    int wbase = 0;
    #pragma unroll
    for (int wq = 0; wq < 4; wq++)
        if (wq < wid) wbase += wsum[wq];
    int off = wbase + inc - cnt;             // exclusive offset
    if (t == 127) totK = off + cnt;

    // emit bit indices in ascending order
    int base0 = (2 * t) << 5;
    while (m0) {
        int b = __ffs(m0) - 1; m0 &= m0 - 1;
        if (off < CAP) nbr[off] = (unsigned short)(base0 + b);
        off++;
    }
    int base1 = (2 * t + 1) << 5;
    while (m1) {
        int b = __ffs(m1) - 1; m1 &= m1 - 1;
        if (off < CAP) nbr[off] = (unsigned short)(base1 + b);
        off++;
    }
    __syncthreads();
    int K = totK;

    int g = t >> 4;    // 0..7: neighbor stream (walks k = g, g+8, g+16, ...)
    int c = t & 15;    // col chunk: half2 cols 4c..4c+3

    const uint4* yv = reinterpret_cast<const uint4*>(g_yh);   // [row][16]

    float2 f0 = make_float2(0.f, 0.f), f1 = f0, f2 = f0, f3 = f0;

    if (K <= CAP) {
        int k = g;
        for (; k + 24 < K; k += 32) {
            int j0 = nbr[k], j1 = nbr[k + 8], j2 = nbr[k + 16], j3 = nbr[k + 24];
            uint4 v0 = yv[j0 * 16 + c];
            uint4 v1 = yv[j1 * 16 + c];
            uint4 v2 = yv[j2 * 16 + c];
            uint4 v3 = yv[j3 * 16 + c];
            unsigned s0 = hadd2(hadd2(v0.x, v1.x), hadd2(v2.x, v3.x));
            unsigned s1 = hadd2(hadd2(v0.y, v1.y), hadd2(v2.y, v3.y));
            unsigned s2 = hadd2(hadd2(v0.z, v1.z), hadd2(v2.z, v3.z));
            unsigned s3 = hadd2(hadd2(v0.w, v1.w), hadd2(v2.w, v3.w));
            float2 q0 = __half22float2(*reinterpret_cast<__half2*>(&s0));
            float2 q1 = __half22float2(*reinterpret_cast<__half2*>(&s1));
            float2 q2 = __half22float2(*reinterpret_cast<__half2*>(&s2));
            float2 q3 = __half22float2(*reinterpret_cast<__half2*>(&s3));
            f0.x += q0.x; f0.y += q0.y;
            f1.x += q1.x; f1.y += q1.y;
            f2.x += q2.x; f2.y += q2.y;
            f3.x += q3.x; f3.y += q3.y;
        }
        for (; k < K; k += 8) {
            uint4 v = yv[nbr[k] * 16 + c];
            float2 q0 = __half22float2(*reinterpret_cast<__half2*>(&v.x));
            float2 q1 = __half22float2(*reinterpret_cast<__half2*>(&v.y));
            float2 q2 = __half22float2(*reinterpret_cast<__half2*>(&v.z));
            float2 q3 = __half22float2(*reinterpret_cast<__half2*>(&v.w));
            f0.x += q0.x; f0.y += q0.y;
            f1.x += q1.x; f1.y += q1.y;
            f2.x += q2.x; f2.y += q2.y;
            f3.x += q3.x; f3.y += q3.y;
        }
    } else {
        // overflow fallback — structurally impossible here, kept for safety.
        // group 0 serially scans the mask row from global.
        if (g == 0) {
            for (int w = 0; w < words; w++) {
                unsigned m = g_mask[(size_t)i * words + w];
                while (m) {
                    int b = __ffs(m) - 1; m &= m - 1;
                    int j = (w << 5) + b;
                    uint4 v = yv[j * 16 + c];
                    float2 q0 = __half22float2(*reinterpret_cast<__half2*>(&v.x));
                    float2 q1 = __half22float2(*reinterpret_cast<__half2*>(&v.y));
                    float2 q2 = __half22float2(*reinterpret_cast<__half2*>(&v.z));
                    float2 q3 = __half22float2(*reinterpret_cast<__half2*>(&v.w));
                    f0.x += q0.x; f0.y += q0.y;
                    f1.x += q1.x; f1.y += q1.y;
                    f2.x += q2.x; f2.y += q2.y;
                    f3.x += q3.x; f3.y += q3.y;
                }
            }
        }
    }

    part[g * 64 + 4 * c + 0] = f0;
    part[g * 64 + 4 * c + 1] = f1;
    part[g * 64 + 4 * c + 2] = f2;
    part[g * 64 + 4 * c + 3] = f3;
    __syncthreads();

    if (t < 64) {
        float2 s = part[t];
        #pragma unroll
        for (int q = 1; q < 8; q++) {
            float2 pv = part[q * 64 + t];
            s.x += pv.x; s.y += pv.y;
        }
        float dv = rsqrtf((float)g_deg[i] + 1e-8f);
        float2 bb = reinterpret_cast<const float2*>(bias)[t];
        float2 o;
        o.x = fmaf(dv, s.x, bb.x);
        o.y = fmaf(dv, s.y, bb.y);
        reinterpret_cast<float2*>(out)[(size_t)i * 64 + t] = o;
    }
}

// ---------------------------------------------------------------------------
extern "C" void kernel_launch(void* const* d_in, const int* in_sizes, int n_in,
                              void* d_out, int out_size) {
    const float* x    = (const float*)d_in[0];
    const int*   edge = (const int*)d_in[1];
    const float* W    = (const float*)d_in[2];
    const float* b    = (const float*)d_in[3];
    float*       out  = (float*)d_out;

    int N = in_sizes[0] / D;        // 8192
    int E = in_sizes[1] / 2;        // 262144
    int n_words = (N * N) >> 5;

    k_zero<<<1024, 256>>>(W, n_words, N);
    int total = E + N;
    k_build<<<(total + 255) / 256, 256>>>(edge, E, N);
    k_gemm_y<<<(N + BR - 1) / BR, 256>>>(x, N);
    k_aggregate<<<N, D>>>(b, out, N);
}